// round 16
// baseline (speedup 1.0000x reference)
#include <cuda_runtime.h>
#include <cuda_bf16.h>
#include <math.h>

typedef unsigned int u32;
typedef unsigned long long ull;

#define NB 65536
#define NK 16
#define SCALE 0.125f

// ---------------- scratch (device globals; no allocation APIs) ----------------
__device__ float g_U[(size_t)NB * 512];        // [B, H*D] 128MB
__device__ float g_CTX[(size_t)NB * 512];      // [B, H*D] 128MB
__device__ float g_CONTEXT[(size_t)NB * 256];  // [B, D]    64MB
__device__ float g_M[512 * 256];               // fused Wk^T·Wq  [h*256+c][d]
__device__ int   g_mask_mode;                  // 0=u8, 1=i32, 2=f32

// ---------------- valid_mask dtype probe ----------------
__global__ void k_detect_mask(const unsigned int* __restrict__ w) {
    if (threadIdx.x == 0 && blockIdx.x == 0) {
        int f32like = 1, i32like = 1;
        for (int i = 0; i < 64; i++) {
            unsigned v = w[i];
            if (v != 0u && v != 0x3F800000u) f32like = 0;
            if (v > 1u) i32like = 0;
        }
        g_mask_mode = f32like ? 2 : (i32like ? 1 : 0);
    }
}

__device__ __forceinline__ float maskval(const void* p, int b, int mode) {
    if (mode == 0) return ((const unsigned char*)p)[b] ? 1.0f : 0.0f;
    if (mode == 1) return ((const int*)p)[b] ? 1.0f : 0.0f;
    return (((const float*)p)[b] != 0.0f) ? 1.0f : 0.0f;
}

// ---------------- precompute M_h = Wk_h^T @ Wq_h : g_M[h*256+c][d] ----------------
__global__ void __launch_bounds__(256) k_prep_M(const float* __restrict__ Wq,
                                                const float* __restrict__ Wk) {
    __shared__ float sWk[64][8];
    int bx = blockIdx.x;           // 64 blocks
    int h = bx >> 5;
    int c0 = (bx & 31) * 8;
    int t = threadIdx.x;
    for (int i = t; i < 64 * 8; i += 256) {
        int a = i >> 3, j = i & 7;
        sWk[a][j] = Wk[h * 16384 + a * 256 + c0 + j];
    }
    __syncthreads();
    int d = t;
    float acc[8] = {0, 0, 0, 0, 0, 0, 0, 0};
    for (int a = 0; a < 64; a++) {
        float w = Wq[h * 16384 + a * 256 + d];
#pragma unroll
        for (int j = 0; j < 8; j++) acc[j] += sWk[a][j] * w;
    }
#pragma unroll
    for (int j = 0; j < 8; j++)
        g_M[(h * 256 + c0 + j) * 256 + d] = acc[j];
}

// ---------------- bf16 / f32x2 helpers ----------------
__device__ __forceinline__ u32 bf2(float lo, float hi) {
    u32 r;
    asm("cvt.rn.bf16x2.f32 %0, %2, %1;" : "=r"(r) : "f"(lo), "f"(hi));
    return r;
}
__device__ __forceinline__ ull pack2(float lo, float hi) {
    ull v; asm("mov.b64 %0, {%1, %2};" : "=l"(v) : "f"(lo), "f"(hi)); return v;
}
__device__ __forceinline__ void unpack2(ull v, float& lo, float& hi) {
    asm("mov.b64 {%0, %1}, %2;" : "=f"(lo), "=f"(hi) : "l"(v));
}
#define FMA2(accv, av, bv) asm("fma.rn.f32x2 %0, %1, %2, %0;" : "+l"(accv) : "l"(av), "l"(bv))

#define MMA_BF16(acc, a, b)                                                     \
    asm volatile(                                                               \
        "mma.sync.aligned.m16n8k16.row.col.f32.bf16.bf16.f32 "                  \
        "{%0,%1,%2,%3},{%4,%5,%6,%7},{%8,%9},{%0,%1,%2,%3};"                    \
        : "+f"((acc)[0]), "+f"((acc)[1]), "+f"((acc)[2]), "+f"((acc)[3])        \
        : "r"((a)[0]), "r"((a)[1]), "r"((a)[2]), "r"((a)[3]),                   \
          "r"((b)[0]), "r"((b)[1]))

__device__ __forceinline__ void ldsm_x4(u32& r0, u32& r1, u32& r2, u32& r3, u32 addr) {
    asm volatile("ldmatrix.sync.aligned.m8n8.x4.shared.b16 {%0,%1,%2,%3}, [%4];"
                 : "=r"(r0), "=r"(r1), "=r"(r2), "=r"(r3) : "r"(addr));
}

__device__ __forceinline__ float gatemix(float x, float cv, float cx) {
    float g = 1.0f / (1.0f + expf(-x));
    return g * cv + (1.0f - g) * cx;
}

// ---------------- tensor-core GEMM: C[M,N] = A[M,K] @ Bw[N,K]^T ----------------
// BM=128, BN=128, BK=32. 256 threads = 8 warps (2m x 4n), warp tile 64x32.
// fp32 accuracy via 2-term bf16 split: Ah*Bh + Al*Bh + Ah*Bl.
// Fragments loaded via ldmatrix.x4 from stride-20-word padded smem (conflict-free).
template <int AMODE, int EPI>
__device__ __forceinline__ void gemm_mma(const float* __restrict__ A, int lda,
                                         const float* __restrict__ Bw, int ldb,
                                         float* __restrict__ C, int ldc, int Kdim,
                                         const float* __restrict__ center,
                                         const void* __restrict__ maskp,
                                         const float* __restrict__ ctxin) {
    __shared__ u32 sAh[128 * 20];
    __shared__ u32 sAl[128 * 20];
    __shared__ u32 sBh[128 * 20];
    __shared__ u32 sBl[128 * 20];

    int t = threadIdx.x;
    int warp = t >> 5, lane = t & 31;
    int g = lane >> 2, t4 = lane & 3;
    int warp_m = warp & 1, warp_n = warp >> 1;
    int m0 = blockIdx.x * 128, n0 = blockIdx.y * 128;
    int mmode = (AMODE != 0 || EPI == 1) ? g_mask_mode : 0;

    u32 bAh = (u32)__cvta_generic_to_shared(sAh);
    u32 bAl = (u32)__cvta_generic_to_shared(sAl);
    u32 bBh = (u32)__cvta_generic_to_shared(sBh);
    u32 bBl = (u32)__cvta_generic_to_shared(sBl);

    // ldmatrix per-lane addresses (byte offsets into the stride-20-word tiles)
    int q = lane >> 3;
    u32 aoff[4], boff[2];
#pragma unroll
    for (int mi = 0; mi < 4; mi++) {
        int row = warp_m * 64 + mi * 16 + (q & 1) * 8 + (lane & 7);
        aoff[mi] = 4u * (row * 20 + (q >> 1) * 4);
    }
#pragma unroll
    for (int nip = 0; nip < 2; nip++) {
        int row = warp_n * 32 + nip * 16 + (q >> 1) * 8 + (lane & 7);
        boff[nip] = 4u * (row * 20 + (q & 1) * 4);
    }

    float acc[4][4][4];
#pragma unroll
    for (int mi = 0; mi < 4; mi++)
#pragma unroll
        for (int ni = 0; ni < 4; ni++)
#pragma unroll
            for (int e = 0; e < 4; e++) acc[mi][ni][e] = 0.0f;

    int lr = t >> 1;            // tile row 0..127
    int lhalf = t & 1;          // which 16-float half of BK=32
    int sbase = lr * 20 + lhalf * 8;

    for (int k0 = 0; k0 < Kdim; k0 += 32) {
        // ---- A tile: 128 x 32 fp32 -> split bf16 ----
        {
            int row = m0 + lr;
            int kg = k0 + lhalf * 16;
            const float* src;
            float fm = 1.0f;
            if (AMODE == 0) {
                src = &A[(size_t)row * lda + kg];
            } else if (AMODE == 1) {
                src = &center[(size_t)row * 256 + kg];
                fm = maskval(maskp, row, mmode);
            } else {
                if (kg < 256) {
                    src = &center[(size_t)row * 256 + kg];
                    fm = maskval(maskp, row, mmode);
                } else {
                    src = &ctxin[(size_t)row * 256 + (kg - 256)];
                }
            }
            float av[16];
#pragma unroll
            for (int i = 0; i < 4; i++) {
                float4 v = ((const float4*)src)[i];
                av[4 * i + 0] = v.x * fm; av[4 * i + 1] = v.y * fm;
                av[4 * i + 2] = v.z * fm; av[4 * i + 3] = v.w * fm;
            }
#pragma unroll
            for (int i = 0; i < 8; i++) {
                float x0 = av[2 * i], x1 = av[2 * i + 1];
                __nv_bfloat16 h0 = __float2bfloat16(x0), h1 = __float2bfloat16(x1);
                float r0 = x0 - __bfloat162float(h0);
                float r1 = x1 - __bfloat162float(h1);
                __nv_bfloat162 hp; hp.x = h0; hp.y = h1;
                sAh[sbase + i] = *(u32*)&hp;
                sAl[sbase + i] = bf2(r0, r1);
            }
        }
        // ---- B tile: 128 x 32 fp32 (weights, [N][K] row-major) ----
        {
            const float* src = &Bw[(size_t)(n0 + lr) * ldb + k0 + lhalf * 16];
            float bv[16];
#pragma unroll
            for (int i = 0; i < 4; i++) {
                float4 v = ((const float4*)src)[i];
                bv[4 * i + 0] = v.x; bv[4 * i + 1] = v.y;
                bv[4 * i + 2] = v.z; bv[4 * i + 3] = v.w;
            }
#pragma unroll
            for (int i = 0; i < 8; i++) {
                float x0 = bv[2 * i], x1 = bv[2 * i + 1];
                __nv_bfloat16 h0 = __float2bfloat16(x0), h1 = __float2bfloat16(x1);
                float r0 = x0 - __bfloat162float(h0);
                float r1 = x1 - __bfloat162float(h1);
                __nv_bfloat162 hp; hp.x = h0; hp.y = h1;
                sBh[sbase + i] = *(u32*)&hp;
                sBl[sbase + i] = bf2(r0, r1);
            }
        }
        __syncthreads();

#pragma unroll
        for (int kk = 0; kk < 2; kk++) {
            u32 kadd = kk * 32;  // 8 words
            u32 ah[4][4], al[4][4], bh[2][4], bl[2][4];
#pragma unroll
            for (int mi = 0; mi < 4; mi++) {
                ldsm_x4(ah[mi][0], ah[mi][1], ah[mi][2], ah[mi][3], bAh + aoff[mi] + kadd);
                ldsm_x4(al[mi][0], al[mi][1], al[mi][2], al[mi][3], bAl + aoff[mi] + kadd);
            }
#pragma unroll
            for (int nip = 0; nip < 2; nip++) {
                ldsm_x4(bh[nip][0], bh[nip][1], bh[nip][2], bh[nip][3], bBh + boff[nip] + kadd);
                ldsm_x4(bl[nip][0], bl[nip][1], bl[nip][2], bl[nip][3], bBl + boff[nip] + kadd);
            }
#pragma unroll
            for (int mi = 0; mi < 4; mi++)
#pragma unroll
                for (int ni = 0; ni < 4; ni++) {
                    u32* bhp = &bh[ni >> 1][(ni & 1) * 2];
                    u32* blp = &bl[ni >> 1][(ni & 1) * 2];
                    MMA_BF16(acc[mi][ni], ah[mi], bhp);
                    MMA_BF16(acc[mi][ni], al[mi], bhp);
                    MMA_BF16(acc[mi][ni], ah[mi], blp);
                }
        }
        __syncthreads();
    }

    // ---- epilogue ----
#pragma unroll
    for (int mi = 0; mi < 4; mi++) {
        int r0 = m0 + warp_m * 64 + mi * 16 + g;
#pragma unroll
        for (int ni = 0; ni < 4; ni++) {
            int cn = n0 + warp_n * 32 + ni * 8 + 2 * t4;
            float* a = acc[mi][ni];
            if (EPI == 0) {
                *(float2*)&C[(size_t)r0 * ldc + cn] = make_float2(a[0], a[1]);
                *(float2*)&C[(size_t)(r0 + 8) * ldc + cn] = make_float2(a[2], a[3]);
            } else {
                float fm0 = maskval(maskp, r0, mmode);
                float fm1 = maskval(maskp, r0 + 8, mmode);
                float2 cv0 = *(const float2*)&center[(size_t)r0 * 256 + cn];
                float2 cv1 = *(const float2*)&center[(size_t)(r0 + 8) * 256 + cn];
                float2 cx0 = *(const float2*)&ctxin[(size_t)r0 * 256 + cn];
                float2 cx1 = *(const float2*)&ctxin[(size_t)(r0 + 8) * 256 + cn];
                float2 o0, o1;
                o0.x = gatemix(a[0], cv0.x * fm0, cx0.x);
                o0.y = gatemix(a[1], cv0.y * fm0, cx0.y);
                o1.x = gatemix(a[2], cv1.x * fm1, cx1.x);
                o1.y = gatemix(a[3], cv1.y * fm1, cx1.y);
                *(float2*)&C[(size_t)r0 * ldc + cn] = o0;
                *(float2*)&C[(size_t)(r0 + 8) * ldc + cn] = o1;
            }
        }
    }
}

// ---------------- GEMM entry kernels ----------------
__global__ void __launch_bounds__(256) k_gemm_u(const float* __restrict__ center,
                                                const void* __restrict__ mask) {
    gemm_mma<1, 0>(nullptr, 0, g_M, 256, g_U, 512, 256, center, mask, nullptr);
}
__global__ void __launch_bounds__(256) k_gemm_ctx(const float* __restrict__ Wproj) {
    gemm_mma<0, 0>(g_CTX, 512, Wproj, 512, g_CONTEXT, 256, 512, nullptr, nullptr, nullptr);
}
__global__ void __launch_bounds__(256) k_gemm_gate(const float* __restrict__ Wgate,
                                                   const float* __restrict__ center,
                                                   const void* __restrict__ mask,
                                                   float* __restrict__ out) {
    gemm_mma<2, 1>(nullptr, 0, Wgate, 512, out, 256, 512, center, mask, g_CONTEXT);
}

// ---------------- attention: register-resident columns, shfl score reduce ----------------
// 128 threads/block, thread t owns columns (2t, 2t+1) of the 16x256 neighbor tile.
__global__ void __launch_bounds__(128) k_attn(const float* __restrict__ neigh,
                                              const float* __restrict__ conf) {
    __shared__ float sPart[32 * 4];   // [(h,k)][warp]
    __shared__ float sW[32];          // softmax weights

    int b = blockIdx.x;
    int t = threadIdx.x;
    int warp = t >> 5, lane = t & 31;

    const float* nb = neigh + (size_t)b * 4096 + 2 * t;
    float2 n[NK];
#pragma unroll
    for (int k = 0; k < NK; k++)
        n[k] = __ldcs((const float2*)(nb + k * 256));

    const float* Ub = g_U + (size_t)b * 512 + 2 * t;
    float2 u0 = *(const float2*)Ub;
    float2 u1 = *(const float2*)(Ub + 256);

    // scores: per-k partial, immediate warp butterfly, lane0 stores warp sum
#pragma unroll
    for (int k = 0; k < NK; k++) {
        float p0 = u0.x * n[k].x + u0.y * n[k].y;
        float p1 = u1.x * n[k].x + u1.y * n[k].y;
#pragma unroll
        for (int off = 16; off; off >>= 1) {
            p0 += __shfl_xor_sync(0xffffffffu, p0, off);
            p1 += __shfl_xor_sync(0xffffffffu, p1, off);
        }
        if (lane == 0) {
            sPart[k * 4 + warp] = p0;
            sPart[(16 + k) * 4 + warp] = p1;
        }
    }
    __syncthreads();

    // warp 0: combine 4 warp-partials, add log-conf, softmax per 16-lane head group
    if (t < 32) {
        float4 qv = *(const float4*)&sPart[t * 4];
        float s = (qv.x + qv.y) + (qv.z + qv.w);
        int k = t & 15;
        float lc = __logf(fmaxf(conf[(size_t)b * NK + k], 1e-8f));
        s = s * SCALE + lc;
        float m = s;
#pragma unroll
        for (int off = 8; off; off >>= 1)
            m = fmaxf(m, __shfl_xor_sync(0xffffffffu, m, off));
        float e = __expf(s - m);
        float sum = e;
#pragma unroll
        for (int off = 8; off; off >>= 1)
            sum += __shfl_xor_sync(0xffffffffu, sum, off);
        sW[t] = e / sum;
    }
    __syncthreads();

    // ctx: weighted sum over k from registers (packed f32x2 FMA)
    float* outp = g_CTX + (size_t)b * 512 + 2 * t;
#pragma unroll
    for (int h = 0; h < 2; h++) {
        ull acc = 0ull;
#pragma unroll
        for (int k = 0; k < NK; k++) {
            float w = sW[h * 16 + k];
            FMA2(acc, pack2(n[k].x, n[k].y), pack2(w, w));
        }
        float lo, hi;
        unpack2(acc, lo, hi);
        *(float2*)(outp + h * 256) = make_float2(lo, hi);
    }
}

// ---------------- launch ----------------
extern "C" void kernel_launch(void* const* d_in, const int* in_sizes, int n_in,
                              void* d_out, int out_size) {
    const float* center = (const float*)d_in[0];
    const float* neigh  = (const float*)d_in[1];
    const float* conf   = (const float*)d_in[2];
    const void*  mask   = d_in[3];
    const float* Wq     = (const float*)d_in[4];
    const float* Wk     = (const float*)d_in[5];
    const float* Wproj  = (const float*)d_in[6];
    const float* Wgate  = (const float*)d_in[7];
    float* out = (float*)d_out;

    k_detect_mask<<<1, 32>>>((const unsigned int*)mask);
    k_prep_M<<<64, 256>>>(Wq, Wk);

    k_gemm_u<<<dim3(NB / 128, 4), 256>>>(center, mask);

    k_attn<<<NB, 128>>>(neigh, conf);

    k_gemm_ctx<<<dim3(NB / 128, 2), 256>>>(Wproj);
    k_gemm_gate<<<dim3(NB / 128, 2), 256>>>(Wgate, center, mask, out);
}

// round 17
// speedup vs baseline: 1.2304x; 1.2304x over previous
#include <cuda_runtime.h>
#include <cuda_bf16.h>
#include <math.h>

typedef unsigned int u32;
typedef unsigned long long ull;

#define NB 65536
#define NK 16
#define SCALE 0.125f
#define GEMM_SMEM 81920

// ---------------- scratch (device globals; no allocation APIs) ----------------
__device__ float g_U[(size_t)NB * 512];         // attn logits operand [B, H*D]
__device__ float g_CONTEXT[(size_t)NB * 256];   // projected context fp32
__device__ u32 g_CXh[(size_t)NB * 256];         // attn ctx split (bf16x2 hi), [B,512]->256 u32
__device__ u32 g_CXl[(size_t)NB * 256];
__device__ u32 g_CPh[(size_t)NB * 128];         // projected context split [B,256]->128 u32
__device__ u32 g_CPl[(size_t)NB * 128];
__device__ u32 g_Ch[(size_t)NB * 128];          // masked center split [B,256]->128 u32
__device__ u32 g_Cl[(size_t)NB * 128];
__device__ float g_M[512 * 256];                // fused Wk^T·Wq
__device__ u32 g_Mh[512 * 128], g_Ml[512 * 128];
__device__ u32 g_Ph[256 * 256], g_Pl[256 * 256];
__device__ u32 g_Gh[256 * 256], g_Gl[256 * 256];
__device__ int g_mask_mode;                     // 0=u8, 1=i32, 2=f32

// ---------------- helpers ----------------
__device__ __forceinline__ u32 bf2(float lo, float hi) {
    u32 r;
    asm("cvt.rn.bf16x2.f32 %0, %2, %1;" : "=r"(r) : "f"(lo), "f"(hi));
    return r;
}
__device__ __forceinline__ void split2(float x0, float x1, u32& h, u32& l) {
    __nv_bfloat16 b0 = __float2bfloat16(x0), b1 = __float2bfloat16(x1);
    __nv_bfloat162 hp; hp.x = b0; hp.y = b1;
    h = *(u32*)&hp;
    l = bf2(x0 - __bfloat162float(b0), x1 - __bfloat162float(b1));
}
__device__ __forceinline__ ull pack2(float lo, float hi) {
    ull v; asm("mov.b64 %0, {%1, %2};" : "=l"(v) : "f"(lo), "f"(hi)); return v;
}
__device__ __forceinline__ void unpack2(ull v, float& lo, float& hi) {
    asm("mov.b64 {%0, %1}, %2;" : "=f"(lo), "=f"(hi) : "l"(v));
}
#define FMA2(accv, av, bv) asm("fma.rn.f32x2 %0, %1, %2, %0;" : "+l"(accv) : "l"(av), "l"(bv))

#define MMA_BF16(acc, a, b)                                                     \
    asm volatile(                                                               \
        "mma.sync.aligned.m16n8k16.row.col.f32.bf16.bf16.f32 "                  \
        "{%0,%1,%2,%3},{%4,%5,%6,%7},{%8,%9},{%0,%1,%2,%3};"                    \
        : "+f"((acc)[0]), "+f"((acc)[1]), "+f"((acc)[2]), "+f"((acc)[3])        \
        : "r"((a)[0]), "r"((a)[1]), "r"((a)[2]), "r"((a)[3]),                   \
          "r"((b)[0]), "r"((b)[1]))

__device__ __forceinline__ void ldsm_x4(u32& r0, u32& r1, u32& r2, u32& r3, u32 addr) {
    asm volatile("ldmatrix.sync.aligned.m8n8.x4.shared.b16 {%0,%1,%2,%3}, [%4];"
                 : "=r"(r0), "=r"(r1), "=r"(r2), "=r"(r3) : "r"(addr));
}
#define CP_ASYNC16(dst, src) \
    asm volatile("cp.async.cg.shared.global [%0], [%1], 16;" :: "r"(dst), "l"(src))
#define CP_COMMIT() asm volatile("cp.async.commit_group;")
#define CP_WAIT1() asm volatile("cp.async.wait_group 1;")
#define CP_WAIT0() asm volatile("cp.async.wait_group 0;")

__device__ __forceinline__ float maskval(const void* p, int b, int mode) {
    if (mode == 0) return ((const unsigned char*)p)[b] ? 1.0f : 0.0f;
    if (mode == 1) return ((const int*)p)[b] ? 1.0f : 0.0f;
    return (((const float*)p)[b] != 0.0f) ? 1.0f : 0.0f;
}
__device__ __forceinline__ float gatemix(float x, float cv, float cx) {
    float g = 1.0f / (1.0f + expf(-x));
    return g * cv + (1.0f - g) * cx;
}

// ---------------- mask dtype probe ----------------
__global__ void k_detect_mask(const unsigned int* __restrict__ w) {
    if (threadIdx.x == 0 && blockIdx.x == 0) {
        int f32like = 1, i32like = 1;
        for (int i = 0; i < 64; i++) {
            unsigned v = w[i];
            if (v != 0u && v != 0x3F800000u) f32like = 0;
            if (v > 1u) i32like = 0;
        }
        g_mask_mode = f32like ? 2 : (i32like ? 1 : 0);
    }
}

// ---------------- M_h = Wk_h^T @ Wq_h ----------------
__global__ void __launch_bounds__(256) k_prep_M(const float* __restrict__ Wq,
                                                const float* __restrict__ Wk) {
    __shared__ float sWk[64][8];
    int bx = blockIdx.x;
    int h = bx >> 5;
    int c0 = (bx & 31) * 8;
    int t = threadIdx.x;
    for (int i = t; i < 64 * 8; i += 256) {
        int a = i >> 3, j = i & 7;
        sWk[a][j] = Wk[h * 16384 + a * 256 + c0 + j];
    }
    __syncthreads();
    int d = t;
    float acc[8] = {0, 0, 0, 0, 0, 0, 0, 0};
    for (int a = 0; a < 64; a++) {
        float w = Wq[h * 16384 + a * 256 + d];
#pragma unroll
        for (int j = 0; j < 8; j++) acc[j] += sWk[a][j] * w;
    }
#pragma unroll
    for (int j = 0; j < 8; j++)
        g_M[(h * 256 + c0 + j) * 256 + d] = acc[j];
}

// ---------------- pre-split weights and center ----------------
__global__ void __launch_bounds__(256) k_split_weights(const float* __restrict__ Wproj,
                                                       const float* __restrict__ Wgate) {
    int i = blockIdx.x * 256 + threadIdx.x;   // 768 blocks -> 196608 pairs
    const float* src; u32 *dh, *dl; int j;
    if (i < 65536)       { src = g_M;   dh = g_Mh; dl = g_Ml; j = i; }
    else if (i < 131072) { src = Wproj; dh = g_Ph; dl = g_Pl; j = i - 65536; }
    else                 { src = Wgate; dh = g_Gh; dl = g_Gl; j = i - 131072; }
    float2 v = ((const float2*)src)[j];
    split2(v.x, v.y, dh[j], dl[j]);
}

__global__ void __launch_bounds__(256) k_split_center(const float* __restrict__ center,
                                                      const void* __restrict__ mask) {
    size_t p = (size_t)blockIdx.x * 256 + threadIdx.x;   // 32768 blocks
    int b = (int)(p >> 7);
    float fm = maskval(mask, b, g_mask_mode);
    float2 v = ((const float2*)center)[p];
    split2(v.x * fm, v.y * fm, g_Ch[p], g_Cl[p]);
}

// ---------------- tensor-core GEMM: C[M,N] = A[M,K] @ Bw[N,K]^T ----------------
// Operands pre-split bf16x2 (hi/lo). BM=BN=128, BK=32. cp.async 2-stage pipeline.
// CONCAT: A = [Ah (pairs 0..127) | A2h (pairs 128..255)], both lda_u=128.
// EPI: 0 plain store; 1 gate epilogue; 2 store + split to g_CPh/g_CPl.
template <int CONCAT, int EPI>
__device__ __forceinline__ void gemm_mma(
    const u32* __restrict__ Ah, const u32* __restrict__ Al,
    const u32* __restrict__ A2h, const u32* __restrict__ A2l, int lda_u,
    const u32* __restrict__ Bh, const u32* __restrict__ Bl, int ldb_u,
    float* __restrict__ C, int ldc, int Kdim,
    const float* __restrict__ center, const void* __restrict__ maskp) {

    extern __shared__ u32 smem[];  // 2 stages x 4 tiles x 2560 u32 (stride-20 rows)
    int t = threadIdx.x;
    int warp = t >> 5, lane = t & 31;
    int g = lane >> 2, t4 = lane & 3;
    int warp_m = warp & 1, warp_n = warp >> 1;
    int n0 = blockIdx.x * 128, m0 = blockIdx.y * 128;
    int mmode = (EPI == 1) ? g_mask_mode : 0;

    u32 sb = (u32)__cvta_generic_to_shared(smem);
    int lr = t >> 1, lhalf = t & 1;
    u32 dst_row = 4u * (lr * 20 + lhalf * 8);

    // ldmatrix per-lane byte offsets within one 10240B tile
    int q = lane >> 3;
    u32 aoff[4], boff[2];
#pragma unroll
    for (int mi = 0; mi < 4; mi++) {
        int row = warp_m * 64 + mi * 16 + (q & 1) * 8 + (lane & 7);
        aoff[mi] = 4u * (row * 20 + (q >> 1) * 4);
    }
#pragma unroll
    for (int nip = 0; nip < 2; nip++) {
        int row = warp_n * 32 + nip * 16 + (q >> 1) * 8 + (lane & 7);
        boff[nip] = 4u * (row * 20 + (q & 1) * 4);
    }

    float acc[4][4][4];
#pragma unroll
    for (int mi = 0; mi < 4; mi++)
#pragma unroll
        for (int ni = 0; ni < 4; ni++)
#pragma unroll
            for (int e = 0; e < 4; e++) acc[mi][ni][e] = 0.0f;

    int KT = Kdim >> 5;   // 32 elems (16 pairs) per tile

#define ISSUE_TILE(kt, s)                                                        \
    do {                                                                         \
        int kp = (kt) * 16 + lhalf * 8;                                          \
        const u32 *pah, *pal; int kc;                                            \
        if (!CONCAT || kp < 128) { pah = Ah; pal = Al; kc = kp; }                \
        else { pah = A2h; pal = A2l; kc = kp - 128; }                            \
        const u32* sa_h = pah + (size_t)(m0 + lr) * lda_u + kc;                  \
        const u32* sa_l = pal + (size_t)(m0 + lr) * lda_u + kc;                  \
        const u32* sb_h = Bh + (size_t)(n0 + lr) * ldb_u + (kt) * 16 + lhalf * 8;\
        const u32* sb_l = Bl + (size_t)(n0 + lr) * ldb_u + (kt) * 16 + lhalf * 8;\
        u32 d0 = sb + (s) * 40960u + dst_row;                                    \
        CP_ASYNC16(d0, sa_h);            CP_ASYNC16(d0 + 16, sa_h + 4);          \
        CP_ASYNC16(d0 + 10240, sa_l);    CP_ASYNC16(d0 + 10256, sa_l + 4);       \
        CP_ASYNC16(d0 + 20480, sb_h);    CP_ASYNC16(d0 + 20496, sb_h + 4);       \
        CP_ASYNC16(d0 + 30720, sb_l);    CP_ASYNC16(d0 + 30736, sb_l + 4);       \
        CP_COMMIT();                                                             \
    } while (0)

    ISSUE_TILE(0, 0);
    for (int kt = 0; kt < KT; kt++) {
        int s = kt & 1;
        if (kt + 1 < KT) { ISSUE_TILE(kt + 1, (kt + 1) & 1); CP_WAIT1(); }
        else             { CP_WAIT0(); }
        __syncthreads();

        u32 base = sb + s * 40960u;
#pragma unroll
        for (int kk = 0; kk < 2; kk++) {
            u32 kadd = kk * 32;
            u32 ah[4][4], al[4][4], bh[2][4], bl[2][4];
#pragma unroll
            for (int mi = 0; mi < 4; mi++) {
                ldsm_x4(ah[mi][0], ah[mi][1], ah[mi][2], ah[mi][3], base + aoff[mi] + kadd);
                ldsm_x4(al[mi][0], al[mi][1], al[mi][2], al[mi][3], base + 10240 + aoff[mi] + kadd);
            }
#pragma unroll
            for (int nip = 0; nip < 2; nip++) {
                ldsm_x4(bh[nip][0], bh[nip][1], bh[nip][2], bh[nip][3], base + 20480 + boff[nip] + kadd);
                ldsm_x4(bl[nip][0], bl[nip][1], bl[nip][2], bl[nip][3], base + 30720 + boff[nip] + kadd);
            }
#pragma unroll
            for (int mi = 0; mi < 4; mi++)
#pragma unroll
                for (int ni = 0; ni < 4; ni++) {
                    u32* bhp = &bh[ni >> 1][(ni & 1) * 2];
                    u32* blp = &bl[ni >> 1][(ni & 1) * 2];
                    MMA_BF16(acc[mi][ni], ah[mi], bhp);
                    MMA_BF16(acc[mi][ni], al[mi], bhp);
                    MMA_BF16(acc[mi][ni], ah[mi], blp);
                }
        }
        __syncthreads();
    }
#undef ISSUE_TILE

    // ---- epilogue ----
#pragma unroll
    for (int mi = 0; mi < 4; mi++) {
        int r0 = m0 + warp_m * 64 + mi * 16 + g;
#pragma unroll
        for (int ni = 0; ni < 4; ni++) {
            int cn = n0 + warp_n * 32 + ni * 8 + 2 * t4;
            float* a = acc[mi][ni];
            if (EPI == 0) {
                *(float2*)&C[(size_t)r0 * ldc + cn] = make_float2(a[0], a[1]);
                *(float2*)&C[(size_t)(r0 + 8) * ldc + cn] = make_float2(a[2], a[3]);
            } else if (EPI == 2) {
                *(float2*)&C[(size_t)r0 * ldc + cn] = make_float2(a[0], a[1]);
                *(float2*)&C[(size_t)(r0 + 8) * ldc + cn] = make_float2(a[2], a[3]);
                u32 h0, l0, h1, l1;
                split2(a[0], a[1], h0, l0);
                split2(a[2], a[3], h1, l1);
                size_t p0 = (size_t)r0 * 128 + (cn >> 1);
                size_t p1 = (size_t)(r0 + 8) * 128 + (cn >> 1);
                g_CPh[p0] = h0; g_CPl[p0] = l0;
                g_CPh[p1] = h1; g_CPl[p1] = l1;
            } else {
                float fm0 = maskval(maskp, r0, mmode);
                float fm1 = maskval(maskp, r0 + 8, mmode);
                float2 cv0 = *(const float2*)&center[(size_t)r0 * 256 + cn];
                float2 cv1 = *(const float2*)&center[(size_t)(r0 + 8) * 256 + cn];
                float2 cx0 = *(const float2*)&g_CONTEXT[(size_t)r0 * 256 + cn];
                float2 cx1 = *(const float2*)&g_CONTEXT[(size_t)(r0 + 8) * 256 + cn];
                float2 o0, o1;
                o0.x = gatemix(a[0], cv0.x * fm0, cx0.x);
                o0.y = gatemix(a[1], cv0.y * fm0, cx0.y);
                o1.x = gatemix(a[2], cv1.x * fm1, cx1.x);
                o1.y = gatemix(a[3], cv1.y * fm1, cx1.y);
                *(float2*)&C[(size_t)r0 * ldc + cn] = o0;
                *(float2*)&C[(size_t)(r0 + 8) * ldc + cn] = o1;
            }
        }
    }
}

// ---------------- GEMM entry kernels ----------------
__global__ void __launch_bounds__(256) k_gemm_u() {
    gemm_mma<0, 0>(g_Ch, g_Cl, nullptr, nullptr, 128, g_Mh, g_Ml, 128,
                   g_U, 512, 256, nullptr, nullptr);
}
__global__ void __launch_bounds__(256) k_gemm_ctx() {
    gemm_mma<0, 2>(g_CXh, g_CXl, nullptr, nullptr, 256, g_Ph, g_Pl, 256,
                   g_CONTEXT, 256, 512, nullptr, nullptr);
}
__global__ void __launch_bounds__(256) k_gemm_gate(const float* __restrict__ center,
                                                   const void* __restrict__ mask,
                                                   float* __restrict__ out) {
    gemm_mma<1, 1>(g_Ch, g_Cl, g_CPh, g_CPl, 128, g_Gh, g_Gl, 256,
                   out, 256, 512, center, mask);
}

// ---------------- attention: register-resident, split bf16 output ----------------
__global__ void __launch_bounds__(128) k_attn(const float* __restrict__ neigh,
                                              const float* __restrict__ conf) {
    __shared__ float sPart[32 * 4];
    __shared__ float sW[32];

    int b = blockIdx.x;
    int t = threadIdx.x;
    int warp = t >> 5, lane = t & 31;

    const float* nb = neigh + (size_t)b * 4096 + 2 * t;
    float2 n[NK];
#pragma unroll
    for (int k = 0; k < NK; k++)
        n[k] = __ldcs((const float2*)(nb + k * 256));

    const float* Ub = g_U + (size_t)b * 512 + 2 * t;
    float2 u0 = *(const float2*)Ub;
    float2 u1 = *(const float2*)(Ub + 256);

#pragma unroll
    for (int k = 0; k < NK; k++) {
        float p0 = u0.x * n[k].x + u0.y * n[k].y;
        float p1 = u1.x * n[k].x + u1.y * n[k].y;
#pragma unroll
        for (int off = 16; off; off >>= 1) {
            p0 += __shfl_xor_sync(0xffffffffu, p0, off);
            p1 += __shfl_xor_sync(0xffffffffu, p1, off);
        }
        if (lane == 0) {
            sPart[k * 4 + warp] = p0;
            sPart[(16 + k) * 4 + warp] = p1;
        }
    }
    __syncthreads();

    if (t < 32) {
        float4 qv = *(const float4*)&sPart[t * 4];
        float s = (qv.x + qv.y) + (qv.z + qv.w);
        int k = t & 15;
        float lc = __logf(fmaxf(conf[(size_t)b * NK + k], 1e-8f));
        s = s * SCALE + lc;
        float m = s;
#pragma unroll
        for (int off = 8; off; off >>= 1)
            m = fmaxf(m, __shfl_xor_sync(0xffffffffu, m, off));
        float e = __expf(s - m);
        float sum = e;
#pragma unroll
        for (int off = 8; off; off >>= 1)
            sum += __shfl_xor_sync(0xffffffffu, sum, off);
        sW[t] = e / sum;
    }
    __syncthreads();

#pragma unroll
    for (int hh = 0; hh < 2; hh++) {
        ull acc = 0ull;
#pragma unroll
        for (int k = 0; k < NK; k++) {
            float w = sW[hh * 16 + k];
            FMA2(acc, pack2(n[k].x, n[k].y), pack2(w, w));
        }
        float lo, hi;
        unpack2(acc, lo, hi);
        u32 hw, lw;
        split2(lo, hi, hw, lw);
        size_t p = (size_t)b * 256 + hh * 128 + t;
        g_CXh[p] = hw;
        g_CXl[p] = lw;
    }
}

// ---------------- launch ----------------
extern "C" void kernel_launch(void* const* d_in, const int* in_sizes, int n_in,
                              void* d_out, int out_size) {
    const float* center = (const float*)d_in[0];
    const float* neigh  = (const float*)d_in[1];
    const float* conf   = (const float*)d_in[2];
    const void*  mask   = d_in[3];
    const float* Wq     = (const float*)d_in[4];
    const float* Wk     = (const float*)d_in[5];
    const float* Wproj  = (const float*)d_in[6];
    const float* Wgate  = (const float*)d_in[7];
    float* out = (float*)d_out;

    static int attr_done = 0;
    if (!attr_done) {
        cudaFuncSetAttribute(k_gemm_u,    cudaFuncAttributeMaxDynamicSharedMemorySize, GEMM_SMEM);
        cudaFuncSetAttribute(k_gemm_ctx,  cudaFuncAttributeMaxDynamicSharedMemorySize, GEMM_SMEM);
        cudaFuncSetAttribute(k_gemm_gate, cudaFuncAttributeMaxDynamicSharedMemorySize, GEMM_SMEM);
        attr_done = 1;
    }

    k_detect_mask<<<1, 32>>>((const unsigned int*)mask);
    k_prep_M<<<64, 256>>>(Wq, Wk);
    k_split_weights<<<768, 256>>>(Wproj, Wgate);
    k_split_center<<<32768, 256>>>(center, mask);

    k_gemm_u<<<dim3(4, 512), 256, GEMM_SMEM>>>();

    k_attn<<<NB, 128>>>(neigh, conf);

    k_gemm_ctx<<<dim3(2, 512), 256, GEMM_SMEM>>>();
    k_gemm_gate<<<dim3(2, 512), 256, GEMM_SMEM>>>(center, mask, out);
}